// round 2
// baseline (speedup 1.0000x reference)
#include <cuda_runtime.h>
#include <math.h>

#define H 256
#define W 256
#define HW 65536
#define BATCH 4
#define NSTAT (BATCH*HW)
#define NBLKMAX 1024

#define SZ16 (BATCH*16*HW)
#define SZ18 (BATCH*18*HW)
#define SZ64 (BATCH*64*HW)

// ---------------- scratch (static device globals; no allocations) ----------
__device__ __align__(16) float g_hfpre[SZ16];
__device__ __align__(16) float g_prehf[SZ16];
__device__ __align__(16) float g_pre[SZ16];
__device__ __align__(16) float g_t[SZ16];
__device__ __align__(16) float g_off[SZ18];
__device__ __align__(16) float g_d16[SZ16];
__device__ __align__(16) float g_y[SZ16];
__device__ __align__(16) float g_z[SZ64];
__device__ __align__(16) float g_s[SZ64];
__device__ __align__(16) float g_sp[BATCH*2*HW];
__device__ __align__(16) float g_sg[BATCH*HW];
__device__ __align__(16) float g_xb[4*SZ16];
__device__ float g_bsum[NBLKMAX*64];
__device__ float g_bsq[NBLKMAX*64];
__device__ float g_bmax[NBLKMAX*64];
// stats slots: 0=hf, 1..4=branch outs, 5=pre, 6=y, 7=z, 8=xx, 9=final
// layout per slot: [0..63]=mean, [64..127]=inv
__device__ float g_stats[10*128];
__device__ float g_ca[BATCH*64];

// ---------------- BN finalize (per-channel mean/inv from block partials) ---
__global__ void bn_final_k(int nblk, int slot)
{
    int c = blockIdx.x, lane = threadIdx.x;
    float s = 0.f, q = 0.f;
    for (int j = lane; j < nblk; j += 32) {
        s += g_bsum[j * 64 + c];
        q += g_bsq[j * 64 + c];
    }
    #pragma unroll
    for (int d = 16; d > 0; d >>= 1) {
        s += __shfl_down_sync(0xffffffffu, s, d);
        q += __shfl_down_sync(0xffffffffu, q, d);
    }
    if (lane == 0) {
        float m = s / (float)NSTAT;
        float v = q / (float)NSTAT - m * m;
        g_stats[slot * 128 + c] = m;
        g_stats[slot * 128 + 64 + c] = rsqrtf(v + 1e-5f);
    }
}

// ---------------- generic 3x3 conv with fused norm-on-load + stats ---------
template<int CIN, int COUT, int PIX, bool BIAS, bool NORM, bool RELU, bool ADDEND, int STATS>
__global__ void __launch_bounds__(256) conv3x3_g(
    const float* __restrict__ in, int inCt, int inCo,
    const float* __restrict__ stats,                  // slot base (mean, inv)
    const float* __restrict__ w, int wCt, int wCo,
    const float* __restrict__ bias,
    const float* __restrict__ addend,
    float* __restrict__ out, int dil, int gridX)
{
    constexpr int CCH = (CIN < 16) ? CIN : 16;
    constexpr int COUTP = (COUT + 3) & ~3;
    __shared__ __align__(16) float ws[CCH * 9 * COUTP];
    __shared__ float reds[STATS ? COUT * 8 : 1];
    __shared__ float redq[STATS ? COUT * 8 : 1];
    __shared__ float redm[(STATS == 2) ? COUT * 8 : 1];

    const int tid = threadIdx.x;
    const int b = blockIdx.y;
    const int pix0 = blockIdx.x * (256 * PIX) + tid;

    int py[PIX], px[PIX];
    #pragma unroll
    for (int p = 0; p < PIX; p++) {
        int pix = pix0 + p * 256;
        py[p] = pix >> 8; px[p] = pix & 255;
    }

    float acc[PIX][COUTP];
    #pragma unroll
    for (int p = 0; p < PIX; p++)
        #pragma unroll
        for (int o = 0; o < COUTP; o++)
            acc[p][o] = (BIAS && o < COUT) ? __ldg(&bias[o]) : 0.f;

    for (int c0 = 0; c0 < CIN; c0 += CCH) {
        __syncthreads();
        for (int i = tid; i < CCH * 9 * COUTP; i += 256) {
            int o = i % COUTP;
            int rem = i / COUTP;
            int k = rem % 9;
            int cl = rem / 9;
            ws[i] = (o < COUT) ? w[((size_t)o * wCt + wCo + c0 + cl) * 9 + k] : 0.f;
        }
        __syncthreads();
        #pragma unroll 1
        for (int cl = 0; cl < CCH; cl++) {
            const float* __restrict__ inp = in + (size_t)(b * inCt + inCo + c0 + cl) * HW;
            float iv = 1.f, nm = 0.f;
            if (NORM) {
                float m = stats[c0 + cl];
                iv = stats[64 + c0 + cl];
                nm = -m * iv;
            }
            #pragma unroll
            for (int ky = 0; ky < 3; ky++) {
                #pragma unroll
                for (int kx = 0; kx < 3; kx++) {
                    float v[PIX];
                    #pragma unroll
                    for (int p = 0; p < PIX; p++) {
                        int yy = py[p] + (ky - 1) * dil;
                        int xx = px[p] + (kx - 1) * dil;
                        float t = 0.f;
                        if ((unsigned)yy < (unsigned)H && (unsigned)xx < (unsigned)W) {
                            t = inp[yy * W + xx];
                            if (NORM) t = fmaf(t, iv, nm);
                            if (RELU) t = fmaxf(t, 0.f);
                        }
                        v[p] = t;
                    }
                    const float* wrow = &ws[(cl * 9 + ky * 3 + kx) * COUTP];
                    #pragma unroll
                    for (int o4 = 0; o4 < COUTP / 4; o4++) {
                        float4 wv = *(const float4*)(wrow + 4 * o4);
                        #pragma unroll
                        for (int p = 0; p < PIX; p++) {
                            acc[p][4*o4+0] = fmaf(v[p], wv.x, acc[p][4*o4+0]);
                            acc[p][4*o4+1] = fmaf(v[p], wv.y, acc[p][4*o4+1]);
                            acc[p][4*o4+2] = fmaf(v[p], wv.z, acc[p][4*o4+2]);
                            acc[p][4*o4+3] = fmaf(v[p], wv.w, acc[p][4*o4+3]);
                        }
                    }
                }
            }
        }
    }
    // epilogue: addend + store
    #pragma unroll
    for (int p = 0; p < PIX; p++) {
        int pix = pix0 + p * 256;
        #pragma unroll
        for (int o = 0; o < COUT; o++) {
            float val = acc[p][o];
            if (ADDEND) val += addend[(size_t)(b * COUT + o) * HW + pix];
            out[(size_t)(b * COUT + o) * HW + pix] = val;
            acc[p][o] = val;
        }
    }
    if constexpr (STATS > 0) {
        int lane = tid & 31, wid = tid >> 5;
        #pragma unroll 1
        for (int o = 0; o < COUT; o++) {
            float s = 0.f, q = 0.f, mx = -INFINITY;
            #pragma unroll
            for (int p = 0; p < PIX; p++) {
                float v = acc[p][o];
                s += v; q = fmaf(v, v, q);
                if (STATS == 2) mx = fmaxf(mx, v);
            }
            #pragma unroll
            for (int d = 16; d > 0; d >>= 1) {
                s += __shfl_down_sync(0xffffffffu, s, d);
                q += __shfl_down_sync(0xffffffffu, q, d);
                if (STATS == 2) mx = fmaxf(mx, __shfl_down_sync(0xffffffffu, mx, d));
            }
            if (lane == 0) {
                reds[o * 8 + wid] = s;
                redq[o * 8 + wid] = q;
                if (STATS == 2) redm[o * 8 + wid] = mx;
            }
        }
        __syncthreads();
        if (tid < COUT) {
            float s = 0.f, q = 0.f, mx = -INFINITY;
            #pragma unroll
            for (int j = 0; j < 8; j++) {
                s += reds[tid * 8 + j];
                q += redq[tid * 8 + j];
                if (STATS == 2) mx = fmaxf(mx, redm[tid * 8 + j]);
            }
            int row = b * gridX + blockIdx.x;
            g_bsum[row * 64 + tid] = s;
            g_bsq[row * 64 + tid] = q;
            if (STATS == 2) g_bmax[row * 64 + tid] = mx;
        }
    }
}

// ---------------- 1x1 convs with fused stats --------------------------------
__global__ void __launch_bounds__(256) conv1x1_64_16_k(
    const float* __restrict__ in, const float* __restrict__ w,
    const float* __restrict__ bias, float* __restrict__ out, int gridX)
{
    __shared__ __align__(16) float ws[64*16];
    __shared__ float reds[16*8], redq[16*8];
    int tid = threadIdx.x;
    for (int i = tid; i < 64*16; i += 256) {
        int o = i & 15, c = i >> 4;
        ws[i] = w[o * 64 + c];
    }
    __syncthreads();
    int pix = blockIdx.x * 256 + tid;
    int b = blockIdx.y;
    float acc[16];
    #pragma unroll
    for (int o = 0; o < 16; o++) acc[o] = __ldg(&bias[o]);
    #pragma unroll 1
    for (int c = 0; c < 64; c++) {
        float v = in[(size_t)(b * 64 + c) * HW + pix];
        const float4* wr = (const float4*)&ws[c * 16];
        #pragma unroll
        for (int o4 = 0; o4 < 4; o4++) {
            float4 wv = wr[o4];
            acc[4*o4+0] = fmaf(v, wv.x, acc[4*o4+0]);
            acc[4*o4+1] = fmaf(v, wv.y, acc[4*o4+1]);
            acc[4*o4+2] = fmaf(v, wv.z, acc[4*o4+2]);
            acc[4*o4+3] = fmaf(v, wv.w, acc[4*o4+3]);
        }
    }
    #pragma unroll
    for (int o = 0; o < 16; o++) out[(size_t)(b * 16 + o) * HW + pix] = acc[o];
    // stats
    int lane = tid & 31, wid = tid >> 5;
    #pragma unroll 1
    for (int o = 0; o < 16; o++) {
        float s = acc[o], q = acc[o] * acc[o];
        #pragma unroll
        for (int d = 16; d > 0; d >>= 1) {
            s += __shfl_down_sync(0xffffffffu, s, d);
            q += __shfl_down_sync(0xffffffffu, q, d);
        }
        if (lane == 0) { reds[o*8+wid] = s; redq[o*8+wid] = q; }
    }
    __syncthreads();
    if (tid < 16) {
        float s = 0.f, q = 0.f;
        #pragma unroll
        for (int j = 0; j < 8; j++) { s += reds[tid*8+j]; q += redq[tid*8+j]; }
        int row = b * gridX + blockIdx.x;
        g_bsum[row * 64 + tid] = s;
        g_bsq[row * 64 + tid] = q;
    }
}

__global__ void __launch_bounds__(256) conv1x1_cat4_k(
    const float* __restrict__ xb, const float* __restrict__ w,
    const float* __restrict__ bias, float* __restrict__ out, int gridX)
{
    __shared__ __align__(16) float ws[64*64];
    __shared__ float siv[64], snm[64];
    __shared__ float reds[64*8], redq[64*8];
    int tid = threadIdx.x;
    if (tid < 64) {
        int s = tid >> 4, c = tid & 15;
        float m = g_stats[(1 + s) * 128 + c];
        float iv = g_stats[(1 + s) * 128 + 64 + c];
        siv[tid] = iv; snm[tid] = -m * iv;
    }
    for (int i = tid; i < 64*64; i += 256) {
        int o = i & 63, c = i >> 6;
        ws[i] = w[o * 64 + c];
    }
    __syncthreads();
    int pix = blockIdx.x * 256 + tid;
    int b = blockIdx.y;
    float acc[64];
    #pragma unroll
    for (int o = 0; o < 64; o++) acc[o] = __ldg(&bias[o]);
    #pragma unroll 1
    for (int c = 0; c < 64; c++) {
        const float* src = xb + (size_t)(c >> 4) * SZ16 + (size_t)(b * 16 + (c & 15)) * HW;
        float v = fmaf(src[pix], siv[c], snm[c]);
        const float4* wr = (const float4*)&ws[c * 64];
        #pragma unroll
        for (int o4 = 0; o4 < 16; o4++) {
            float4 wv = wr[o4];
            acc[4*o4+0] = fmaf(v, wv.x, acc[4*o4+0]);
            acc[4*o4+1] = fmaf(v, wv.y, acc[4*o4+1]);
            acc[4*o4+2] = fmaf(v, wv.z, acc[4*o4+2]);
            acc[4*o4+3] = fmaf(v, wv.w, acc[4*o4+3]);
        }
    }
    #pragma unroll
    for (int o = 0; o < 64; o++) out[(size_t)(b * 64 + o) * HW + pix] = acc[o];
    int lane = tid & 31, wid = tid >> 5;
    #pragma unroll 1
    for (int o = 0; o < 64; o++) {
        float s = acc[o], q = acc[o] * acc[o];
        #pragma unroll
        for (int d = 16; d > 0; d >>= 1) {
            s += __shfl_down_sync(0xffffffffu, s, d);
            q += __shfl_down_sync(0xffffffffu, q, d);
        }
        if (lane == 0) { reds[o*8+wid] = s; redq[o*8+wid] = q; }
    }
    __syncthreads();
    if (tid < 64) {
        float s = 0.f, q = 0.f;
        #pragma unroll
        for (int j = 0; j < 8; j++) { s += reds[tid*8+j]; q += redq[tid*8+j]; }
        int row = b * gridX + blockIdx.x;
        g_bsum[row * 64 + tid] = s;
        g_bsq[row * 64 + tid] = q;
    }
}

// ---------------- t materialization (float4) --------------------------------
__global__ void norm_t_k(const float* __restrict__ pre,
                         const float* __restrict__ add1, const float* __restrict__ st1,
                         const float* __restrict__ lfsrc, int lfco)
{
    int i4 = blockIdx.x * 256 + threadIdx.x;  // SZ16/4 elements
    int idx = i4 * 4;
    int pix = idx & (HW - 1);
    int rest = idx >> 16;
    int c = rest & 15, b = rest >> 4;
    float m = g_stats[5 * 128 + c], iv = g_stats[5 * 128 + 64 + c];
    float nm = -m * iv;
    float4 v = ((const float4*)pre)[i4];
    v.x = fmaf(v.x, iv, nm); v.y = fmaf(v.y, iv, nm);
    v.z = fmaf(v.z, iv, nm); v.w = fmaf(v.w, iv, nm);
    if (add1) {
        float4 a = ((const float4*)add1)[i4];
        if (st1) {
            float m1 = st1[c], i1 = st1[64 + c], n1 = -m1 * i1;
            a.x = fmaf(a.x, i1, n1); a.y = fmaf(a.y, i1, n1);
            a.z = fmaf(a.z, i1, n1); a.w = fmaf(a.w, i1, n1);
        }
        v.x += a.x; v.y += a.y; v.z += a.z; v.w += a.w;
    }
    if (lfsrc) {
        float4 l = *(const float4*)(lfsrc + (size_t)(b * 64 + lfco + c) * HW + pix);
        v.x += l.x; v.y += l.y; v.z += l.z; v.w += l.w;
    }
    ((float4*)g_t)[i4] = v;
}

// ---------------- deformable conv (exact reference semantics) ---------------
__global__ void __launch_bounds__(256) deform_k(
    const float* __restrict__ t, const float* __restrict__ off,
    const float* __restrict__ wd, float* __restrict__ out)
{
    __shared__ __align__(16) float ws[16*16*9];
    for (int i = threadIdx.x; i < 2304; i += blockDim.x) {
        int o = i & 15;
        int rem = i >> 4;
        int n = rem % 9;
        int c = rem / 9;
        ws[i] = wd[(o * 16 + c) * 9 + n];
    }
    __syncthreads();
    int pix = blockIdx.x * blockDim.x + threadIdx.x;
    int b = blockIdx.y;
    int yi = pix >> 8, xj = pix & 255;

    float acc[16];
    #pragma unroll
    for (int o = 0; o < 16; o++) acc[o] = 0.f;

    const float* offb = off + (size_t)b * 18 * HW + pix;
    const float* tb = t + (size_t)b * 16 * HW;

    #pragma unroll 1
    for (int n = 0; n < 9; n++) {
        int dx = n / 3 - 1, dy = n % 3 - 1;
        float ox = offb[(size_t)(2 * n) * HW];
        float oy = offb[(size_t)(2 * n + 1) * HW];
        float plx = (float)(yi + 1 + dx) + ox;
        float ply = (float)(xj + 1 + dy) + oy;
        float flx = floorf(plx), fly = floorf(ply);
        int qltx = min(max((int)flx, 0), 257);
        int qlty = min(max((int)fly, 0), 257);
        int qrbx = min(max((int)flx + 1, 0), 257);
        int qrby = min(max((int)fly + 1, 0), 257);
        bool mx = (plx < 1.0f) || (plx > 256.0f);
        bool my = (ply < 1.0f) || (ply > 256.0f);
        float px = mx ? flx : plx; px = fminf(fmaxf(px, 0.f), 257.f);
        float py = my ? fly : ply; py = fminf(fmaxf(py, 0.f), 257.f);
        float wltx = 1.f + ((float)qltx - px);
        float wrbx = 1.f - ((float)qrbx - px);
        float wlty = 1.f + ((float)qlty - py);
        float wrby = 1.f - ((float)qrby - py);
        float glt = wltx * wlty, grb = wrbx * wrby;
        float glb = wltx * wrby, grt = wrbx * wlty;
        bool vltx = (qltx >= 1 && qltx <= 256);
        bool vlty = (qlty >= 1 && qlty <= 256);
        bool vrbx = (qrbx >= 1 && qrbx <= 256);
        bool vrby = (qrby >= 1 && qrby <= 256);
        int rlt = (qltx - 1) * W + (qlty - 1);
        int rrb = (qrbx - 1) * W + (qrby - 1);
        int rlb = (qltx - 1) * W + (qrby - 1);
        int rrt = (qrbx - 1) * W + (qlty - 1);
        #pragma unroll 1
        for (int c = 0; c < 16; c++) {
            const float* tc = tb + (size_t)c * HW;
            float vlt = (vltx && vlty) ? tc[rlt] : 0.f;
            float vrb = (vrbx && vrby) ? tc[rrb] : 0.f;
            float vlb = (vltx && vrby) ? tc[rlb] : 0.f;
            float vrt = (vrbx && vlty) ? tc[rrt] : 0.f;
            float val = glt * vlt + grb * vrb + glb * vlb + grt * vrt;
            const float* wr = &ws[(c * 9 + n) * 16];
            #pragma unroll
            for (int o4 = 0; o4 < 4; o4++) {
                float4 wv = *(const float4*)(wr + 4 * o4);
                acc[4*o4+0] = fmaf(val, wv.x, acc[4*o4+0]);
                acc[4*o4+1] = fmaf(val, wv.y, acc[4*o4+1]);
                acc[4*o4+2] = fmaf(val, wv.z, acc[4*o4+2]);
                acc[4*o4+3] = fmaf(val, wv.w, acc[4*o4+3]);
            }
        }
    }
    #pragma unroll
    for (int o = 0; o < 16; o++) out[(size_t)(b * 16 + o) * HW + pix] = acc[o];
}

// ---------------- CBAM ------------------------------------------------------
// finalize z stats (slot 7) + per-batch avg/max + channel attention MLP
__global__ void cbam_final_k(int gridX, const float* __restrict__ w1,
                             const float* __restrict__ w2)
{
    int t = threadIdx.x;          // 256 threads: t = b*64 + c
    int b = t >> 6, c = t & 63;
    float s = 0.f, q = 0.f, mx = -INFINITY;
    for (int j = 0; j < gridX; j++) {
        int idx = (b * gridX + j) * 64 + c;
        s += g_bsum[idx]; q += g_bsq[idx]; mx = fmaxf(mx, g_bmax[idx]);
    }
    __shared__ float sh_s[4][64], sh_q[4][64], sh_m[4][64];
    sh_s[b][c] = s; sh_q[b][c] = q; sh_m[b][c] = mx;
    __syncthreads();
    __shared__ float sm[64], si[64];
    if (t < 64) {
        float ts = 0.f, tq = 0.f;
        #pragma unroll
        for (int bb = 0; bb < 4; bb++) { ts += sh_s[bb][t]; tq += sh_q[bb][t]; }
        float m = ts / (float)NSTAT;
        float v = tq / (float)NSTAT - m * m;
        float iv = rsqrtf(v + 1e-5f);
        g_stats[7 * 128 + t] = m;
        g_stats[7 * 128 + 64 + t] = iv;
        sm[t] = m; si[t] = iv;
    }
    __syncthreads();
    __shared__ float av[4][64], xmv[4][64];
    av[b][c]  = (sh_s[b][c] / (float)HW - sm[c]) * si[c];
    xmv[b][c] = (sh_m[b][c] - sm[c]) * si[c];
    __syncthreads();
    __shared__ float hid[4][4][2];
    if (t < 32) {
        int bb = t >> 3, h = (t >> 1) & 3, which = t & 1;
        float acc = 0.f;
        for (int cc = 0; cc < 64; cc++)
            acc += w1[h * 64 + cc] * (which ? xmv[bb][cc] : av[bb][cc]);
        hid[bb][h][which] = fmaxf(acc, 0.f);
    }
    __syncthreads();
    {
        float va = 0.f, vm = 0.f;
        #pragma unroll
        for (int h = 0; h < 4; h++) {
            float wv = w2[c * 4 + h];
            va = fmaf(wv, hid[b][h][0], va);
            vm = fmaf(wv, hid[b][h][1], vm);
        }
        g_ca[b * 64 + c] = 1.f / (1.f + expf(-(va + vm)));
    }
}

// sp (mean,max over channels of (z norm * ca)), float4 over pixels
__global__ void apply1_k()
{
    __shared__ float sc[64], sb[64];
    int b = blockIdx.y;
    if (threadIdx.x < 64) {
        int c = threadIdx.x;
        float iv = g_stats[7 * 128 + 64 + c], m = g_stats[7 * 128 + c];
        float s = iv * g_ca[b * 64 + c];
        sc[c] = s; sb[c] = -m * s;
    }
    __syncthreads();
    int p4 = blockIdx.x * 256 + threadIdx.x;   // HW/4 per batch
    const float4* zp = (const float4*)(g_z + (size_t)b * 64 * HW) + p4;
    float4 smv = make_float4(0.f, 0.f, 0.f, 0.f);
    float4 mxv = make_float4(-INFINITY, -INFINITY, -INFINITY, -INFINITY);
    #pragma unroll 1
    for (int c = 0; c < 64; c++) {
        float4 v = zp[(size_t)c * (HW / 4)];
        float s = sc[c], bb = sb[c];
        v.x = fmaf(v.x, s, bb); v.y = fmaf(v.y, s, bb);
        v.z = fmaf(v.z, s, bb); v.w = fmaf(v.w, s, bb);
        smv.x += v.x; smv.y += v.y; smv.z += v.z; smv.w += v.w;
        mxv.x = fmaxf(mxv.x, v.x); mxv.y = fmaxf(mxv.y, v.y);
        mxv.z = fmaxf(mxv.z, v.z); mxv.w = fmaxf(mxv.w, v.w);
    }
    const float k = 1.f / 64.f;
    smv.x *= k; smv.y *= k; smv.z *= k; smv.w *= k;
    ((float4*)(g_sp + (size_t)(b * 2) * HW))[p4] = smv;
    ((float4*)(g_sp + (size_t)(b * 2 + 1) * HW))[p4] = mxv;
}

// sg = sigmoid(conv7x7(sp))
__global__ void apply2_k(const float* __restrict__ wsp)
{
    __shared__ float w[98];
    if (threadIdx.x < 98) w[threadIdx.x] = wsp[threadIdx.x];
    __syncthreads();
    int pix = blockIdx.x * 256 + threadIdx.x;
    int b = blockIdx.y;
    int y = pix >> 8, x = pix & 255;
    const float* s0 = g_sp + (size_t)(b * 2) * HW;
    const float* s1 = s0 + HW;
    float acc = 0.f;
    #pragma unroll 1
    for (int ky = 0; ky < 7; ky++) {
        int yy = y + ky - 3;
        if ((unsigned)yy >= (unsigned)H) continue;
        #pragma unroll
        for (int kx = 0; kx < 7; kx++) {
            int xx = x + kx - 3;
            if ((unsigned)xx >= (unsigned)W) continue;
            int ip = yy * W + xx;
            acc += w[ky * 7 + kx] * s0[ip] + w[49 + ky * 7 + kx] * s1[ip];
        }
    }
    g_sg[(size_t)b * HW + pix] = 1.f / (1.f + expf(-acc));
}

// conv2: 64->16 over (z normalized * ca * sg) computed on load; stats epilogue
__global__ void __launch_bounds__(256) conv2_casg_k(
    const float* __restrict__ w, float* __restrict__ out, int gridX)
{
    constexpr int PIX = 2;
    __shared__ __align__(16) float ws[16 * 9 * 16];
    __shared__ float reds[16 * 8], redq[16 * 8];
    __shared__ float sc[64], sb[64];
    int tid = threadIdx.x, b = blockIdx.y;
    if (tid < 64) {
        float iv = g_stats[7 * 128 + 64 + tid], m = g_stats[7 * 128 + tid];
        float s = iv * g_ca[b * 64 + tid];
        sc[tid] = s; sb[tid] = -m * s;
    }
    int pix0 = blockIdx.x * 512 + tid;
    int py[PIX], px[PIX];
    #pragma unroll
    for (int p = 0; p < PIX; p++) {
        int pix = pix0 + p * 256;
        py[p] = pix >> 8; px[p] = pix & 255;
    }
    // sg taps
    float sgv[PIX][9];
    #pragma unroll
    for (int p = 0; p < PIX; p++)
        #pragma unroll
        for (int kk = 0; kk < 9; kk++) {
            int yy = py[p] + kk / 3 - 1, xx = px[p] + kk % 3 - 1;
            sgv[p][kk] = ((unsigned)yy < (unsigned)H && (unsigned)xx < (unsigned)W)
                         ? g_sg[(size_t)b * HW + yy * W + xx] : 0.f;
        }
    float acc[PIX][16];
    #pragma unroll
    for (int p = 0; p < PIX; p++)
        #pragma unroll
        for (int o = 0; o < 16; o++) acc[p][o] = 0.f;

    for (int c0 = 0; c0 < 64; c0 += 16) {
        __syncthreads();
        for (int i = tid; i < 16 * 9 * 16; i += 256) {
            int o = i & 15;
            int rem = i >> 4;
            int k = rem % 9;
            int cl = rem / 9;
            ws[i] = w[((size_t)o * 64 + c0 + cl) * 9 + k];
        }
        __syncthreads();
        #pragma unroll 1
        for (int cl = 0; cl < 16; cl++) {
            const float* __restrict__ inp = g_z + (size_t)(b * 64 + c0 + cl) * HW;
            float scc = sc[c0 + cl], bcc = sb[c0 + cl];
            #pragma unroll
            for (int kk = 0; kk < 9; kk++) {
                int ky = kk / 3, kx = kk % 3;
                float v[PIX];
                #pragma unroll
                for (int p = 0; p < PIX; p++) {
                    int yy = py[p] + ky - 1, xx = px[p] + kx - 1;
                    float t = 0.f;
                    if ((unsigned)yy < (unsigned)H && (unsigned)xx < (unsigned)W)
                        t = fmaf(inp[yy * W + xx], scc, bcc) * sgv[p][kk];
                    v[p] = t;
                }
                const float* wrow = &ws[(cl * 9 + kk) * 16];
                #pragma unroll
                for (int o4 = 0; o4 < 4; o4++) {
                    float4 wv = *(const float4*)(wrow + 4 * o4);
                    #pragma unroll
                    for (int p = 0; p < PIX; p++) {
                        acc[p][4*o4+0] = fmaf(v[p], wv.x, acc[p][4*o4+0]);
                        acc[p][4*o4+1] = fmaf(v[p], wv.y, acc[p][4*o4+1]);
                        acc[p][4*o4+2] = fmaf(v[p], wv.z, acc[p][4*o4+2]);
                        acc[p][4*o4+3] = fmaf(v[p], wv.w, acc[p][4*o4+3]);
                    }
                }
            }
        }
    }
    #pragma unroll
    for (int p = 0; p < PIX; p++) {
        int pix = pix0 + p * 256;
        #pragma unroll
        for (int o = 0; o < 16; o++)
            out[(size_t)(b * 16 + o) * HW + pix] = acc[p][o];
    }
    int lane = tid & 31, wid = tid >> 5;
    #pragma unroll 1
    for (int o = 0; o < 16; o++) {
        float s = acc[0][o] + acc[1][o];
        float q = fmaf(acc[0][o], acc[0][o], acc[1][o] * acc[1][o]);
        #pragma unroll
        for (int d = 16; d > 0; d >>= 1) {
            s += __shfl_down_sync(0xffffffffu, s, d);
            q += __shfl_down_sync(0xffffffffu, q, d);
        }
        if (lane == 0) { reds[o*8+wid] = s; redq[o*8+wid] = q; }
    }
    __syncthreads();
    if (tid < 16) {
        float s = 0.f, q = 0.f;
        #pragma unroll
        for (int j = 0; j < 8; j++) { s += reds[tid*8+j]; q += redq[tid*8+j]; }
        int row = b * gridX + blockIdx.x;
        g_bsum[row * 64 + tid] = s;
        g_bsq[row * 64 + tid] = q;
    }
}

// ---------------- final elementwise ------------------------------------------
__global__ void norm_s_k(const float* __restrict__ xx, const float* __restrict__ lf)
{
    int i4 = blockIdx.x * 256 + threadIdx.x;   // SZ64/4
    int idx = i4 * 4;
    int c = (idx >> 16) & 63;
    float m = g_stats[8 * 128 + c], iv = g_stats[8 * 128 + 64 + c];
    float nm = -m * iv;
    float4 v = ((const float4*)xx)[i4];
    float4 l = ((const float4*)lf)[i4];
    v.x = fmaxf(fmaf(v.x, iv, nm), 0.f) + l.x;
    v.y = fmaxf(fmaf(v.y, iv, nm), 0.f) + l.y;
    v.z = fmaxf(fmaf(v.z, iv, nm), 0.f) + l.z;
    v.w = fmaxf(fmaf(v.w, iv, nm), 0.f) + l.w;
    ((float4*)g_s)[i4] = v;
}

__global__ void norm_out_k(float* __restrict__ o)
{
    int i4 = blockIdx.x * 256 + threadIdx.x;
    int idx = i4 * 4;
    int c = (idx >> 16) & 63;
    float m = g_stats[9 * 128 + c], iv = g_stats[9 * 128 + 64 + c];
    float nm = -m * iv;
    float4 v = ((float4*)o)[i4];
    v.x = fmaf(v.x, iv, nm); v.y = fmaf(v.y, iv, nm);
    v.z = fmaf(v.z, iv, nm); v.w = fmaf(v.w, iv, nm);
    ((float4*)o)[i4] = v;
}

// ---------------- host orchestration ----------------------------------------
extern "C" void kernel_launch(void* const* d_in, const int* in_sizes, int n_in,
                              void* d_out, int out_size)
{
    const float* lf   = (const float*)d_in[0];
    const float* hf   = (const float*)d_in[1];
    const float* w11  = (const float*)d_in[2];
    const float* b11  = (const float*)d_in[3];
    const float* wconv= (const float*)d_in[4];
    const float* woff = (const float*)d_in[5];
    const float* boff = (const float*)d_in[6];
    const float* wdef = (const float*)d_in[7];
    const float* wdil[4] = {(const float*)d_in[8], (const float*)d_in[9],
                            (const float*)d_in[10], (const float*)d_in[11]};
    const float* wc1  = (const float*)d_in[12];
    const float* wc2  = (const float*)d_in[13];
    const float* wfc1 = (const float*)d_in[14];
    const float* wfc2 = (const float*)d_in[15];
    const float* wsp  = (const float*)d_in[16];
    const float* wc12 = (const float*)d_in[17];
    const float* bc12 = (const float*)d_in[18];
    const float* wc33 = (const float*)d_in[19];
    float* out = (float*)d_out;

    void* tmp;
#define GETP(name, sym) cudaGetSymbolAddress(&tmp, sym); float* name = (float*)tmp;
    GETP(p_hfpre, g_hfpre) GETP(p_prehf, g_prehf) GETP(p_pre, g_pre)
    GETP(p_t, g_t)         GETP(p_off, g_off)     GETP(p_d16, g_d16)
    GETP(p_y, g_y)         GETP(p_z, g_z)         GETP(p_s, g_s)
    GETP(p_xb, g_xb)       GETP(p_stats, g_stats)
#undef GETP

    const dim3 PG1(256, BATCH);   // PIX=1
    const dim3 PG2(128, BATCH);   // PIX=2

    // Stage A: hf_pre = conv1x1(hf)+bias; stats slot0 (consumers apply relu(bn) on load)
    conv1x1_64_16_k<<<PG1, 256>>>(hf, w11, b11, p_hfpre, 256);
    bn_final_k<<<16, 32>>>(1024, 0);

    // Shared hf-part of the branch conv: conv3x3(relu(bn(hf_pre)), wconv[:,16:32])
    conv3x3_g<16,16,2,false,true,true,false,0><<<PG2, 256>>>(
        p_hfpre, 16, 0, p_stats + 0*128, wconv, 32, 16, nullptr, nullptr,
        p_prehf, 1, 0);

    for (int k = 0; k < 4; k++) {
        // pre = conv3x3(prev_norm, wconv[:,0:16]) + prehf ; stats slot5
        if (k == 0)
            conv3x3_g<16,16,2,false,false,false,true,1><<<PG2, 256>>>(
                lf, 64, 0, nullptr, wconv, 32, 0, nullptr, p_prehf, p_pre, 1, 128);
        else
            conv3x3_g<16,16,2,false,true,false,true,1><<<PG2, 256>>>(
                p_xb + (size_t)(k-1) * SZ16, 16, 0, p_stats + k*128,
                wconv, 32, 0, nullptr, p_prehf, p_pre, 1, 128);
        bn_final_k<<<16, 32>>>(512, 5);

        // t = bn(pre) + extras
        const float* add1 = (k >= 1) ? p_xb + (size_t)(k-1) * SZ16 : nullptr;
        const float* st1  = (k >= 1) ? p_stats + k*128 : nullptr;
        const float* lfa  = (k == 0) ? lf : (k == 1) ? lf : (k == 2) ? lf : nullptr;
        int lfco = (k == 0) ? 16 : (k == 1) ? 32 : 48;
        norm_t_k<<<SZ16 / 1024, 256>>>(p_pre, add1, st1, lfa, lfco);

        // offsets + deformable conv
        conv3x3_g<16,18,2,true,false,false,false,0><<<PG2, 256>>>(
            p_t, 16, 0, nullptr, woff, 16, 0, boff, nullptr, p_off, 1, 0);
        deform_k<<<PG1, 256>>>(p_t, p_off, wdef, p_d16);

        // dilated conv ; stats slot6
        conv3x3_g<16,16,2,false,false,false,false,1><<<PG2, 256>>>(
            p_d16, 16, 0, nullptr, wdil[k], 16, 0, nullptr, nullptr, p_y, k + 1, 128);
        bn_final_k<<<16, 32>>>(512, 6);

        // z = conv3x3(bn(y), wc1) ; stats+max slot7 partials
        conv3x3_g<16,64,1,false,true,false,false,2><<<PG1, 256>>>(
            p_y, 16, 0, p_stats + 6*128, wc1, 16, 0, nullptr, nullptr, p_z, 1, 256);
        cbam_final_k<<<1, 256>>>(256, wfc1, wfc2);

        // spatial attention
        apply1_k<<<dim3(64, BATCH), 256>>>();
        apply2_k<<<PG1, 256>>>(wsp);

        // branch output: conv2 with fused norm*ca*sg on load ; stats slot 1+k
        conv2_casg_k<<<PG2, 256>>>(wc2, p_xb + (size_t)k * SZ16, 128);
        bn_final_k<<<16, 32>>>(512, 1 + k);
    }

    // xx_pre = conv1x1(cat4_normalized)+bias ; stats slot8
    conv1x1_cat4_k<<<PG1, 256>>>(p_xb, wc12, bc12, p_z, 256);
    bn_final_k<<<64, 32>>>(1024, 8);
    // s = lf + relu(bn(xx_pre))
    norm_s_k<<<SZ64 / 1024, 256>>>(p_z, lf);

    // out_pre = conv3x3(s, wc33) ; stats slot9 ; normalize in place
    conv3x3_g<64,64,1,false,false,false,false,1><<<PG1, 256>>>(
        p_s, 64, 0, nullptr, wc33, 64, 0, nullptr, nullptr, out, 1, 256);
    bn_final_k<<<64, 32>>>(1024, 9);
    norm_out_k<<<SZ64 / 1024, 256>>>(out);
}

// round 3
// speedup vs baseline: 2.0047x; 2.0047x over previous
#include <cuda_runtime.h>
#include <math.h>

#define H 256
#define W 256
#define HW 65536
#define BATCH 4
#define NSTAT (BATCH*HW)
#define NBLKMAX 1024

#define SZ16 (BATCH*16*HW)
#define SZ18 (BATCH*18*HW)
#define SZ64 (BATCH*64*HW)

// ---------------- scratch (static device globals; no allocations) ----------
__device__ __align__(16) float g_hfpre[SZ16];
__device__ __align__(16) float g_prehf[SZ16];
__device__ __align__(16) float g_pre[SZ16];
__device__ __align__(16) float g_t[SZ16];
__device__ __align__(16) float g_off[SZ18];
__device__ __align__(16) float g_d16[SZ16];
__device__ __align__(16) float g_y[SZ16];
__device__ __align__(16) float g_z[SZ64];
__device__ __align__(16) float g_s[SZ64];
__device__ __align__(16) float g_sp[BATCH*2*HW];
__device__ __align__(16) float g_sg[BATCH*HW];
__device__ __align__(16) float g_xb[4*SZ16];
__device__ float g_bsum[NBLKMAX*64];
__device__ float g_bsq[NBLKMAX*64];
__device__ float g_bmax[NBLKMAX*64];
// stats slots: 0=hf, 1..4=branch outs, 5=pre, 6=y, 7=z, 8=xx, 9=final
// layout per slot: [0..63]=mean, [64..127]=inv
__device__ float g_stats[10*128];
__device__ float g_ca[BATCH*64];

// ---------------- BN finalize ------------------------------------------------
__global__ void bn_final_k(int nblk, int slot)
{
    int c = blockIdx.x, lane = threadIdx.x;
    float s = 0.f, q = 0.f;
    for (int j = lane; j < nblk; j += 32) {
        s += g_bsum[j * 64 + c];
        q += g_bsq[j * 64 + c];
    }
    #pragma unroll
    for (int d = 16; d > 0; d >>= 1) {
        s += __shfl_down_sync(0xffffffffu, s, d);
        q += __shfl_down_sync(0xffffffffu, q, d);
    }
    if (lane == 0) {
        float m = s / (float)NSTAT;
        float v = q / (float)NSTAT - m * m;
        g_stats[slot * 128 + c] = m;
        g_stats[slot * 128 + 64 + c] = rsqrtf(v + 1e-5f);
    }
}

// ---------------- generic 3x3 conv, PIX=1, COUT-split via blockIdx.z ---------
template<int CIN, int COUT, bool BIAS, bool NORM, bool RELU, bool ADDEND, int STATS>
__global__ void __launch_bounds__(256) conv3x3_g(
    const float* __restrict__ in, int inCt, int inCo,
    const float* __restrict__ stats,
    const float* __restrict__ w, int wCt, int wCo,
    const float* __restrict__ bias,
    const float* __restrict__ addend,
    float* __restrict__ out, int outCt,
    int dil)
{
    constexpr int CCH = (CIN < 16) ? CIN : 16;
    constexpr int COUTP = (COUT + 3) & ~3;
    __shared__ __align__(16) float ws[CCH * 9 * COUTP];
    __shared__ float reds[STATS ? COUT * 8 : 1];
    __shared__ float redq[STATS ? COUT * 8 : 1];
    __shared__ float redm[(STATS == 2) ? COUT * 8 : 1];

    const int tid = threadIdx.x;
    const int b = blockIdx.y;
    const int oc0 = blockIdx.z * COUT;
    const int pix = blockIdx.x * 256 + tid;
    const int y = pix >> 8, x = pix & 255;

    // hoisted tap geometry
    bool vy[3], vx[3];
    int yo[3], xo[3];
    #pragma unroll
    for (int t = 0; t < 3; t++) {
        int yy = y + (t - 1) * dil;
        int xx = x + (t - 1) * dil;
        vy[t] = (unsigned)yy < (unsigned)H;
        vx[t] = (unsigned)xx < (unsigned)W;
        yo[t] = yy * W;
        xo[t] = xx;
    }

    float acc[COUTP];
    #pragma unroll
    for (int o = 0; o < COUTP; o++)
        acc[o] = (BIAS && o < COUT) ? __ldg(&bias[oc0 + o]) : 0.f;

    for (int c0 = 0; c0 < CIN; c0 += CCH) {
        __syncthreads();
        for (int i = tid; i < CCH * 9 * COUTP; i += 256) {
            int o = i % COUTP;
            int rem = i / COUTP;
            int k = rem % 9;
            int cl = rem / 9;
            ws[i] = (o < COUT) ? w[((size_t)(oc0 + o) * wCt + wCo + c0 + cl) * 9 + k] : 0.f;
        }
        __syncthreads();
        #pragma unroll 1
        for (int cl = 0; cl < CCH; cl++) {
            const float* __restrict__ inp = in + (size_t)(b * inCt + inCo + c0 + cl) * HW;
            float iv = 1.f, nm = 0.f;
            if (NORM) {
                float m = stats[c0 + cl];
                iv = stats[64 + c0 + cl];
                nm = -m * iv;
            }
            #pragma unroll
            for (int ky = 0; ky < 3; ky++) {
                #pragma unroll
                for (int kx = 0; kx < 3; kx++) {
                    float v = 0.f;
                    if (vy[ky] && vx[kx]) {
                        v = inp[yo[ky] + xo[kx]];
                        if (NORM) v = fmaf(v, iv, nm);
                        if (RELU) v = fmaxf(v, 0.f);
                    }
                    const float* wrow = &ws[(cl * 9 + ky * 3 + kx) * COUTP];
                    #pragma unroll
                    for (int o4 = 0; o4 < COUTP / 4; o4++) {
                        float4 wv = *(const float4*)(wrow + 4 * o4);
                        acc[4*o4+0] = fmaf(v, wv.x, acc[4*o4+0]);
                        acc[4*o4+1] = fmaf(v, wv.y, acc[4*o4+1]);
                        acc[4*o4+2] = fmaf(v, wv.z, acc[4*o4+2]);
                        acc[4*o4+3] = fmaf(v, wv.w, acc[4*o4+3]);
                    }
                }
            }
        }
    }
    // epilogue
    #pragma unroll
    for (int o = 0; o < COUT; o++) {
        float val = acc[o];
        if (ADDEND) val += addend[(size_t)(b * COUT + o) * HW + pix];
        out[(size_t)(b * outCt + oc0 + o) * HW + pix] = val;
        acc[o] = val;
    }
    if constexpr (STATS > 0) {
        int lane = tid & 31, wid = tid >> 5;
        #pragma unroll 1
        for (int o = 0; o < COUT; o++) {
            float s = acc[o], q = acc[o] * acc[o], mx = acc[o];
            #pragma unroll
            for (int d = 16; d > 0; d >>= 1) {
                s += __shfl_down_sync(0xffffffffu, s, d);
                q += __shfl_down_sync(0xffffffffu, q, d);
                if (STATS == 2) mx = fmaxf(mx, __shfl_down_sync(0xffffffffu, mx, d));
            }
            if (lane == 0) {
                reds[o * 8 + wid] = s;
                redq[o * 8 + wid] = q;
                if (STATS == 2) redm[o * 8 + wid] = mx;
            }
        }
        __syncthreads();
        if (tid < COUT) {
            float s = 0.f, q = 0.f, mx = -INFINITY;
            #pragma unroll
            for (int j = 0; j < 8; j++) {
                s += reds[tid * 8 + j];
                q += redq[tid * 8 + j];
                if (STATS == 2) mx = fmaxf(mx, redm[tid * 8 + j]);
            }
            int row = b * gridDim.x + blockIdx.x;
            g_bsum[row * 64 + oc0 + tid] = s;
            g_bsq[row * 64 + oc0 + tid] = q;
            if (STATS == 2) g_bmax[row * 64 + oc0 + tid] = mx;
        }
    }
}

// ---------------- 1x1 convs with fused stats ----------------------------------
__global__ void __launch_bounds__(256) conv1x1_64_16_k(
    const float* __restrict__ in, const float* __restrict__ w,
    const float* __restrict__ bias, float* __restrict__ out)
{
    __shared__ __align__(16) float ws[64*16];
    __shared__ float reds[16*8], redq[16*8];
    int tid = threadIdx.x;
    for (int i = tid; i < 64*16; i += 256) {
        int o = i & 15, c = i >> 4;
        ws[i] = w[o * 64 + c];
    }
    __syncthreads();
    int pix = blockIdx.x * 256 + tid;
    int b = blockIdx.y;
    float acc[16];
    #pragma unroll
    for (int o = 0; o < 16; o++) acc[o] = __ldg(&bias[o]);
    #pragma unroll 1
    for (int c = 0; c < 64; c++) {
        float v = in[(size_t)(b * 64 + c) * HW + pix];
        const float4* wr = (const float4*)&ws[c * 16];
        #pragma unroll
        for (int o4 = 0; o4 < 4; o4++) {
            float4 wv = wr[o4];
            acc[4*o4+0] = fmaf(v, wv.x, acc[4*o4+0]);
            acc[4*o4+1] = fmaf(v, wv.y, acc[4*o4+1]);
            acc[4*o4+2] = fmaf(v, wv.z, acc[4*o4+2]);
            acc[4*o4+3] = fmaf(v, wv.w, acc[4*o4+3]);
        }
    }
    #pragma unroll
    for (int o = 0; o < 16; o++) out[(size_t)(b * 16 + o) * HW + pix] = acc[o];
    int lane = tid & 31, wid = tid >> 5;
    #pragma unroll 1
    for (int o = 0; o < 16; o++) {
        float s = acc[o], q = acc[o] * acc[o];
        #pragma unroll
        for (int d = 16; d > 0; d >>= 1) {
            s += __shfl_down_sync(0xffffffffu, s, d);
            q += __shfl_down_sync(0xffffffffu, q, d);
        }
        if (lane == 0) { reds[o*8+wid] = s; redq[o*8+wid] = q; }
    }
    __syncthreads();
    if (tid < 16) {
        float s = 0.f, q = 0.f;
        #pragma unroll
        for (int j = 0; j < 8; j++) { s += reds[tid*8+j]; q += redq[tid*8+j]; }
        int row = b * gridDim.x + blockIdx.x;
        g_bsum[row * 64 + tid] = s;
        g_bsq[row * 64 + tid] = q;
    }
}

// 64->64 1x1 over normalized cat4; split 2 x 32 outputs via blockIdx.z
__global__ void __launch_bounds__(256) conv1x1_cat4_k(
    const float* __restrict__ xb, const float* __restrict__ w,
    const float* __restrict__ bias, float* __restrict__ out)
{
    __shared__ __align__(16) float ws[64*32];
    __shared__ float siv[64], snm[64];
    __shared__ float reds[32*8], redq[32*8];
    int tid = threadIdx.x;
    int oc0 = blockIdx.z * 32;
    if (tid < 64) {
        int s = tid >> 4, c = tid & 15;
        float m = g_stats[(1 + s) * 128 + c];
        float iv = g_stats[(1 + s) * 128 + 64 + c];
        siv[tid] = iv; snm[tid] = -m * iv;
    }
    for (int i = tid; i < 64*32; i += 256) {
        int o = i & 31, c = i >> 5;
        ws[i] = w[(oc0 + o) * 64 + c];
    }
    __syncthreads();
    int pix = blockIdx.x * 256 + tid;
    int b = blockIdx.y;
    float acc[32];
    #pragma unroll
    for (int o = 0; o < 32; o++) acc[o] = __ldg(&bias[oc0 + o]);
    #pragma unroll 1
    for (int c = 0; c < 64; c++) {
        const float* src = xb + (size_t)(c >> 4) * SZ16 + (size_t)(b * 16 + (c & 15)) * HW;
        float v = fmaf(src[pix], siv[c], snm[c]);
        const float4* wr = (const float4*)&ws[c * 32];
        #pragma unroll
        for (int o4 = 0; o4 < 8; o4++) {
            float4 wv = wr[o4];
            acc[4*o4+0] = fmaf(v, wv.x, acc[4*o4+0]);
            acc[4*o4+1] = fmaf(v, wv.y, acc[4*o4+1]);
            acc[4*o4+2] = fmaf(v, wv.z, acc[4*o4+2]);
            acc[4*o4+3] = fmaf(v, wv.w, acc[4*o4+3]);
        }
    }
    #pragma unroll
    for (int o = 0; o < 32; o++) out[(size_t)(b * 64 + oc0 + o) * HW + pix] = acc[o];
    int lane = tid & 31, wid = tid >> 5;
    #pragma unroll 1
    for (int o = 0; o < 32; o++) {
        float s = acc[o], q = acc[o] * acc[o];
        #pragma unroll
        for (int d = 16; d > 0; d >>= 1) {
            s += __shfl_down_sync(0xffffffffu, s, d);
            q += __shfl_down_sync(0xffffffffu, q, d);
        }
        if (lane == 0) { reds[o*8+wid] = s; redq[o*8+wid] = q; }
    }
    __syncthreads();
    if (tid < 32) {
        float s = 0.f, q = 0.f;
        #pragma unroll
        for (int j = 0; j < 8; j++) { s += reds[tid*8+j]; q += redq[tid*8+j]; }
        int row = b * gridDim.x + blockIdx.x;
        g_bsum[row * 64 + oc0 + tid] = s;
        g_bsq[row * 64 + oc0 + tid] = q;
    }
}

// ---------------- t materialization (float4) ----------------------------------
__global__ void norm_t_k(const float* __restrict__ pre,
                         const float* __restrict__ add1, const float* __restrict__ st1,
                         const float* __restrict__ lfsrc, int lfco)
{
    int i4 = blockIdx.x * 256 + threadIdx.x;  // SZ16/4 elements
    int idx = i4 * 4;
    int pix = idx & (HW - 1);
    int rest = idx >> 16;
    int c = rest & 15, b = rest >> 4;
    float m = g_stats[5 * 128 + c], iv = g_stats[5 * 128 + 64 + c];
    float nm = -m * iv;
    float4 v = ((const float4*)pre)[i4];
    v.x = fmaf(v.x, iv, nm); v.y = fmaf(v.y, iv, nm);
    v.z = fmaf(v.z, iv, nm); v.w = fmaf(v.w, iv, nm);
    if (add1) {
        float4 a = ((const float4*)add1)[i4];
        if (st1) {
            float m1 = st1[c], i1 = st1[64 + c], n1 = -m1 * i1;
            a.x = fmaf(a.x, i1, n1); a.y = fmaf(a.y, i1, n1);
            a.z = fmaf(a.z, i1, n1); a.w = fmaf(a.w, i1, n1);
        }
        v.x += a.x; v.y += a.y; v.z += a.z; v.w += a.w;
    }
    if (lfsrc) {
        float4 l = *(const float4*)(lfsrc + (size_t)(b * 64 + lfco + c) * HW + pix);
        v.x += l.x; v.y += l.y; v.z += l.z; v.w += l.w;
    }
    ((float4*)g_t)[i4] = v;
}

// ---------------- deformable conv (exact reference semantics) ------------------
__global__ void __launch_bounds__(256) deform_k(
    const float* __restrict__ t, const float* __restrict__ off,
    const float* __restrict__ wd, float* __restrict__ out)
{
    __shared__ __align__(16) float ws[16*16*9];
    for (int i = threadIdx.x; i < 2304; i += blockDim.x) {
        int o = i & 15;
        int rem = i >> 4;
        int n = rem % 9;
        int c = rem / 9;
        ws[i] = wd[(o * 16 + c) * 9 + n];
    }
    __syncthreads();
    int pix = blockIdx.x * blockDim.x + threadIdx.x;
    int b = blockIdx.y;
    int yi = pix >> 8, xj = pix & 255;

    float acc[16];
    #pragma unroll
    for (int o = 0; o < 16; o++) acc[o] = 0.f;

    const float* offb = off + (size_t)b * 18 * HW + pix;
    const float* tb = t + (size_t)b * 16 * HW;

    #pragma unroll 1
    for (int n = 0; n < 9; n++) {
        int dx = n / 3 - 1, dy = n % 3 - 1;
        float ox = offb[(size_t)(2 * n) * HW];
        float oy = offb[(size_t)(2 * n + 1) * HW];
        float plx = (float)(yi + 1 + dx) + ox;
        float ply = (float)(xj + 1 + dy) + oy;
        float flx = floorf(plx), fly = floorf(ply);
        int qltx = min(max((int)flx, 0), 257);
        int qlty = min(max((int)fly, 0), 257);
        int qrbx = min(max((int)flx + 1, 0), 257);
        int qrby = min(max((int)fly + 1, 0), 257);
        bool mx = (plx < 1.0f) || (plx > 256.0f);
        bool my = (ply < 1.0f) || (ply > 256.0f);
        float px = mx ? flx : plx; px = fminf(fmaxf(px, 0.f), 257.f);
        float py = my ? fly : ply; py = fminf(fmaxf(py, 0.f), 257.f);
        float wltx = 1.f + ((float)qltx - px);
        float wrbx = 1.f - ((float)qrbx - px);
        float wlty = 1.f + ((float)qlty - py);
        float wrby = 1.f - ((float)qrby - py);
        float glt = wltx * wlty, grb = wrbx * wrby;
        float glb = wltx * wrby, grt = wrbx * wlty;
        bool vltx = (qltx >= 1 && qltx <= 256);
        bool vlty = (qlty >= 1 && qlty <= 256);
        bool vrbx = (qrbx >= 1 && qrbx <= 256);
        bool vrby = (qrby >= 1 && qrby <= 256);
        int rlt = (qltx - 1) * W + (qlty - 1);
        int rrb = (qrbx - 1) * W + (qrby - 1);
        int rlb = (qltx - 1) * W + (qrby - 1);
        int rrt = (qrbx - 1) * W + (qlty - 1);
        #pragma unroll 1
        for (int c = 0; c < 16; c++) {
            const float* tc = tb + (size_t)c * HW;
            float vlt = (vltx && vlty) ? tc[rlt] : 0.f;
            float vrb = (vrbx && vrby) ? tc[rrb] : 0.f;
            float vlb = (vltx && vrby) ? tc[rlb] : 0.f;
            float vrt = (vrbx && vlty) ? tc[rrt] : 0.f;
            float val = glt * vlt + grb * vrb + glb * vlb + grt * vrt;
            const float* wr = &ws[(c * 9 + n) * 16];
            #pragma unroll
            for (int o4 = 0; o4 < 4; o4++) {
                float4 wv = *(const float4*)(wr + 4 * o4);
                acc[4*o4+0] = fmaf(val, wv.x, acc[4*o4+0]);
                acc[4*o4+1] = fmaf(val, wv.y, acc[4*o4+1]);
                acc[4*o4+2] = fmaf(val, wv.z, acc[4*o4+2]);
                acc[4*o4+3] = fmaf(val, wv.w, acc[4*o4+3]);
            }
        }
    }
    #pragma unroll
    for (int o = 0; o < 16; o++) out[(size_t)(b * 16 + o) * HW + pix] = acc[o];
}

// ---------------- CBAM ----------------------------------------------------------
__global__ void cbam_final_k(int gridX, const float* __restrict__ w1,
                             const float* __restrict__ w2)
{
    int t = threadIdx.x;          // 256 threads: t = b*64 + c
    int b = t >> 6, c = t & 63;
    float s = 0.f, q = 0.f, mx = -INFINITY;
    for (int j = 0; j < gridX; j++) {
        int idx = (b * gridX + j) * 64 + c;
        s += g_bsum[idx]; q += g_bsq[idx]; mx = fmaxf(mx, g_bmax[idx]);
    }
    __shared__ float sh_s[4][64], sh_q[4][64], sh_m[4][64];
    sh_s[b][c] = s; sh_q[b][c] = q; sh_m[b][c] = mx;
    __syncthreads();
    __shared__ float sm[64], si[64];
    if (t < 64) {
        float ts = 0.f, tq = 0.f;
        #pragma unroll
        for (int bb = 0; bb < 4; bb++) { ts += sh_s[bb][t]; tq += sh_q[bb][t]; }
        float m = ts / (float)NSTAT;
        float v = tq / (float)NSTAT - m * m;
        float iv = rsqrtf(v + 1e-5f);
        g_stats[7 * 128 + t] = m;
        g_stats[7 * 128 + 64 + t] = iv;
        sm[t] = m; si[t] = iv;
    }
    __syncthreads();
    __shared__ float av[4][64], xmv[4][64];
    av[b][c]  = (sh_s[b][c] / (float)HW - sm[c]) * si[c];
    xmv[b][c] = (sh_m[b][c] - sm[c]) * si[c];
    __syncthreads();
    __shared__ float hid[4][4][2];
    if (t < 32) {
        int bb = t >> 3, h = (t >> 1) & 3, which = t & 1;
        float acc = 0.f;
        for (int cc = 0; cc < 64; cc++)
            acc += w1[h * 64 + cc] * (which ? xmv[bb][cc] : av[bb][cc]);
        hid[bb][h][which] = fmaxf(acc, 0.f);
    }
    __syncthreads();
    {
        float va = 0.f, vm = 0.f;
        #pragma unroll
        for (int h = 0; h < 4; h++) {
            float wv = w2[c * 4 + h];
            va = fmaf(wv, hid[b][h][0], va);
            vm = fmaf(wv, hid[b][h][1], vm);
        }
        g_ca[b * 64 + c] = 1.f / (1.f + expf(-(va + vm)));
    }
}

// sp (mean,max over channels of (z norm * ca)), float4 over pixels
__global__ void apply1_k()
{
    __shared__ float sc[64], sb[64];
    int b = blockIdx.y;
    if (threadIdx.x < 64) {
        int c = threadIdx.x;
        float iv = g_stats[7 * 128 + 64 + c], m = g_stats[7 * 128 + c];
        float s = iv * g_ca[b * 64 + c];
        sc[c] = s; sb[c] = -m * s;
    }
    __syncthreads();
    int p4 = blockIdx.x * 256 + threadIdx.x;   // HW/4 per batch
    const float4* zp = (const float4*)(g_z + (size_t)b * 64 * HW) + p4;
    float4 smv = make_float4(0.f, 0.f, 0.f, 0.f);
    float4 mxv = make_float4(-INFINITY, -INFINITY, -INFINITY, -INFINITY);
    #pragma unroll 1
    for (int c = 0; c < 64; c++) {
        float4 v = zp[(size_t)c * (HW / 4)];
        float s = sc[c], bb = sb[c];
        v.x = fmaf(v.x, s, bb); v.y = fmaf(v.y, s, bb);
        v.z = fmaf(v.z, s, bb); v.w = fmaf(v.w, s, bb);
        smv.x += v.x; smv.y += v.y; smv.z += v.z; smv.w += v.w;
        mxv.x = fmaxf(mxv.x, v.x); mxv.y = fmaxf(mxv.y, v.y);
        mxv.z = fmaxf(mxv.z, v.z); mxv.w = fmaxf(mxv.w, v.w);
    }
    const float k = 1.f / 64.f;
    smv.x *= k; smv.y *= k; smv.z *= k; smv.w *= k;
    ((float4*)(g_sp + (size_t)(b * 2) * HW))[p4] = smv;
    ((float4*)(g_sp + (size_t)(b * 2 + 1) * HW))[p4] = mxv;
}

// sg = sigmoid(conv7x7(sp))
__global__ void apply2_k(const float* __restrict__ wsp)
{
    __shared__ float w[98];
    if (threadIdx.x < 98) w[threadIdx.x] = wsp[threadIdx.x];
    __syncthreads();
    int pix = blockIdx.x * 256 + threadIdx.x;
    int b = blockIdx.y;
    int y = pix >> 8, x = pix & 255;
    const float* s0 = g_sp + (size_t)(b * 2) * HW;
    const float* s1 = s0 + HW;
    float acc = 0.f;
    #pragma unroll 1
    for (int ky = 0; ky < 7; ky++) {
        int yy = y + ky - 3;
        if ((unsigned)yy >= (unsigned)H) continue;
        #pragma unroll
        for (int kx = 0; kx < 7; kx++) {
            int xx = x + kx - 3;
            if ((unsigned)xx >= (unsigned)W) continue;
            int ip = yy * W + xx;
            acc += w[ky * 7 + kx] * s0[ip] + w[49 + ky * 7 + kx] * s1[ip];
        }
    }
    g_sg[(size_t)b * HW + pix] = 1.f / (1.f + expf(-acc));
}

// conv2: 64->16 over (z normalized * ca * sg) computed on load; stats epilogue
__global__ void __launch_bounds__(256) conv2_casg_k(
    const float* __restrict__ w, float* __restrict__ out)
{
    __shared__ __align__(16) float ws[16 * 9 * 16];
    __shared__ float reds[16 * 8], redq[16 * 8];
    __shared__ float sc[64], sb[64];
    int tid = threadIdx.x, b = blockIdx.y;
    if (tid < 64) {
        float iv = g_stats[7 * 128 + 64 + tid], m = g_stats[7 * 128 + tid];
        float s = iv * g_ca[b * 64 + tid];
        sc[tid] = s; sb[tid] = -m * s;
    }
    int pix = blockIdx.x * 256 + tid;
    int y = pix >> 8, x = pix & 255;
    // sg taps + geometry
    bool vy[3], vx[3];
    int yo[3], xo[3];
    float sgv[9];
    #pragma unroll
    for (int t = 0; t < 3; t++) {
        int yy = y + t - 1, xx = x + t - 1;
        vy[t] = (unsigned)yy < (unsigned)H;
        vx[t] = (unsigned)xx < (unsigned)W;
        yo[t] = yy * W; xo[t] = xx;
    }
    #pragma unroll
    for (int kk = 0; kk < 9; kk++) {
        int ky = kk / 3, kx = kk % 3;
        sgv[kk] = (vy[ky] && vx[kx]) ? g_sg[(size_t)b * HW + yo[ky] + xo[kx]] : 0.f;
    }
    float acc[16];
    #pragma unroll
    for (int o = 0; o < 16; o++) acc[o] = 0.f;

    for (int c0 = 0; c0 < 64; c0 += 16) {
        __syncthreads();
        for (int i = tid; i < 16 * 9 * 16; i += 256) {
            int o = i & 15;
            int rem = i >> 4;
            int k = rem % 9;
            int cl = rem / 9;
            ws[i] = w[((size_t)o * 64 + c0 + cl) * 9 + k];
        }
        __syncthreads();
        #pragma unroll 1
        for (int cl = 0; cl < 16; cl++) {
            const float* __restrict__ inp = g_z + (size_t)(b * 64 + c0 + cl) * HW;
            float scc = sc[c0 + cl], bcc = sb[c0 + cl];
            #pragma unroll
            for (int kk = 0; kk < 9; kk++) {
                int ky = kk / 3, kx = kk % 3;
                float v = 0.f;
                if (vy[ky] && vx[kx])
                    v = fmaf(inp[yo[ky] + xo[kx]], scc, bcc) * sgv[kk];
                const float* wrow = &ws[(cl * 9 + kk) * 16];
                #pragma unroll
                for (int o4 = 0; o4 < 4; o4++) {
                    float4 wv = *(const float4*)(wrow + 4 * o4);
                    acc[4*o4+0] = fmaf(v, wv.x, acc[4*o4+0]);
                    acc[4*o4+1] = fmaf(v, wv.y, acc[4*o4+1]);
                    acc[4*o4+2] = fmaf(v, wv.z, acc[4*o4+2]);
                    acc[4*o4+3] = fmaf(v, wv.w, acc[4*o4+3]);
                }
            }
        }
    }
    #pragma unroll
    for (int o = 0; o < 16; o++)
        out[(size_t)(b * 16 + o) * HW + pix] = acc[o];
    int lane = tid & 31, wid = tid >> 5;
    #pragma unroll 1
    for (int o = 0; o < 16; o++) {
        float s = acc[o], q = acc[o] * acc[o];
        #pragma unroll
        for (int d = 16; d > 0; d >>= 1) {
            s += __shfl_down_sync(0xffffffffu, s, d);
            q += __shfl_down_sync(0xffffffffu, q, d);
        }
        if (lane == 0) { reds[o*8+wid] = s; redq[o*8+wid] = q; }
    }
    __syncthreads();
    if (tid < 16) {
        float s = 0.f, q = 0.f;
        #pragma unroll
        for (int j = 0; j < 8; j++) { s += reds[tid*8+j]; q += redq[tid*8+j]; }
        int row = b * gridDim.x + blockIdx.x;
        g_bsum[row * 64 + tid] = s;
        g_bsq[row * 64 + tid] = q;
    }
}

// ---------------- final elementwise ----------------------------------------------
__global__ void norm_s_k(const float* __restrict__ xx, const float* __restrict__ lf)
{
    int i4 = blockIdx.x * 256 + threadIdx.x;   // SZ64/4
    int idx = i4 * 4;
    int c = (idx >> 16) & 63;
    float m = g_stats[8 * 128 + c], iv = g_stats[8 * 128 + 64 + c];
    float nm = -m * iv;
    float4 v = ((const float4*)xx)[i4];
    float4 l = ((const float4*)lf)[i4];
    v.x = fmaxf(fmaf(v.x, iv, nm), 0.f) + l.x;
    v.y = fmaxf(fmaf(v.y, iv, nm), 0.f) + l.y;
    v.z = fmaxf(fmaf(v.z, iv, nm), 0.f) + l.z;
    v.w = fmaxf(fmaf(v.w, iv, nm), 0.f) + l.w;
    ((float4*)g_s)[i4] = v;
}

__global__ void norm_out_k(float* __restrict__ o)
{
    int i4 = blockIdx.x * 256 + threadIdx.x;
    int idx = i4 * 4;
    int c = (idx >> 16) & 63;
    float m = g_stats[9 * 128 + c], iv = g_stats[9 * 128 + 64 + c];
    float nm = -m * iv;
    float4 v = ((float4*)o)[i4];
    v.x = fmaf(v.x, iv, nm); v.y = fmaf(v.y, iv, nm);
    v.z = fmaf(v.z, iv, nm); v.w = fmaf(v.w, iv, nm);
    ((float4*)o)[i4] = v;
}

// ---------------- host orchestration ----------------------------------------------
extern "C" void kernel_launch(void* const* d_in, const int* in_sizes, int n_in,
                              void* d_out, int out_size)
{
    const float* lf   = (const float*)d_in[0];
    const float* hf   = (const float*)d_in[1];
    const float* w11  = (const float*)d_in[2];
    const float* b11  = (const float*)d_in[3];
    const float* wconv= (const float*)d_in[4];
    const float* woff = (const float*)d_in[5];
    const float* boff = (const float*)d_in[6];
    const float* wdef = (const float*)d_in[7];
    const float* wdil[4] = {(const float*)d_in[8], (const float*)d_in[9],
                            (const float*)d_in[10], (const float*)d_in[11]};
    const float* wc1  = (const float*)d_in[12];
    const float* wc2  = (const float*)d_in[13];
    const float* wfc1 = (const float*)d_in[14];
    const float* wfc2 = (const float*)d_in[15];
    const float* wsp  = (const float*)d_in[16];
    const float* wc12 = (const float*)d_in[17];
    const float* bc12 = (const float*)d_in[18];
    const float* wc33 = (const float*)d_in[19];
    float* out = (float*)d_out;

    void* tmp;
#define GETP(name, sym) cudaGetSymbolAddress(&tmp, sym); float* name = (float*)tmp;
    GETP(p_hfpre, g_hfpre) GETP(p_prehf, g_prehf) GETP(p_pre, g_pre)
    GETP(p_t, g_t)         GETP(p_off, g_off)     GETP(p_d16, g_d16)
    GETP(p_y, g_y)         GETP(p_z, g_z)         GETP(p_s, g_s)
    GETP(p_xb, g_xb)       GETP(p_stats, g_stats)
#undef GETP

    const dim3 PG(256, BATCH);          // 1024 blocks, 1 out-split
    const dim3 PG4(256, BATCH, 4);      // 4-way COUT split (64 outs as 4x16)
    const dim3 PGc(256, BATCH, 2);      // 2-way split for 1x1 cat

    // Stage A: hf_pre = conv1x1(hf)+bias; stats slot0
    conv1x1_64_16_k<<<PG, 256>>>(hf, w11, b11, p_hfpre);
    bn_final_k<<<16, 32>>>(1024, 0);

    // Shared hf-part: conv3x3(relu(bn(hf_pre)), wconv[:,16:32])
    conv3x3_g<16,16,false,true,true,false,0><<<PG, 256>>>(
        p_hfpre, 16, 0, p_stats + 0*128, wconv, 32, 16, nullptr, nullptr,
        p_prehf, 16, 1);

    for (int k = 0; k < 4; k++) {
        // pre = conv3x3(prev_norm, wconv[:,0:16]) + prehf ; stats slot5
        if (k == 0)
            conv3x3_g<16,16,false,false,false,true,1><<<PG, 256>>>(
                lf, 64, 0, nullptr, wconv, 32, 0, nullptr, p_prehf, p_pre, 16, 1);
        else
            conv3x3_g<16,16,false,true,false,true,1><<<PG, 256>>>(
                p_xb + (size_t)(k-1) * SZ16, 16, 0, p_stats + k*128,
                wconv, 32, 0, nullptr, p_prehf, p_pre, 16, 1);
        bn_final_k<<<16, 32>>>(1024, 5);

        // t = bn(pre) + extras
        const float* add1 = (k >= 1) ? p_xb + (size_t)(k-1) * SZ16 : nullptr;
        const float* st1  = (k >= 1) ? p_stats + k*128 : nullptr;
        const float* lfa  = (k <= 2) ? lf : nullptr;
        int lfco = (k == 0) ? 16 : (k == 1) ? 32 : 48;
        norm_t_k<<<SZ16 / 1024, 256>>>(p_pre, add1, st1, lfa, lfco);

        // offsets + deformable conv
        conv3x3_g<16,18,true,false,false,false,0><<<PG, 256>>>(
            p_t, 16, 0, nullptr, woff, 16, 0, boff, nullptr, p_off, 18, 1);
        deform_k<<<PG, 256>>>(p_t, p_off, wdef, p_d16);

        // dilated conv ; stats slot6
        conv3x3_g<16,16,false,false,false,false,1><<<PG, 256>>>(
            p_d16, 16, 0, nullptr, wdil[k], 16, 0, nullptr, nullptr, p_y, 16, k + 1);
        bn_final_k<<<16, 32>>>(1024, 6);

        // z = conv3x3(bn(y), wc1) 16->64 split 4x16 ; stats+max slot7 partials
        conv3x3_g<16,16,false,true,false,false,2><<<PG4, 256>>>(
            p_y, 16, 0, p_stats + 6*128, wc1, 16, 0, nullptr, nullptr, p_z, 64, 1);
        cbam_final_k<<<1, 256>>>(256, wfc1, wfc2);

        // spatial attention
        apply1_k<<<dim3(64, BATCH), 256>>>();
        apply2_k<<<PG, 256>>>(wsp);

        // branch output: conv2 with fused norm*ca*sg on load ; stats slot 1+k
        conv2_casg_k<<<PG, 256>>>(wc2, p_xb + (size_t)k * SZ16);
        bn_final_k<<<16, 32>>>(1024, 1 + k);
    }

    // xx_pre = conv1x1(cat4_normalized)+bias ; stats slot8
    conv1x1_cat4_k<<<PGc, 256>>>(p_xb, wc12, bc12, p_z);
    bn_final_k<<<64, 32>>>(1024, 8);
    // s = lf + relu(bn(xx_pre))
    norm_s_k<<<SZ64 / 1024, 256>>>(p_z, lf);

    // out_pre = conv3x3(s, wc33) 64->64 split 4x16 ; stats slot9 ; normalize
    conv3x3_g<64,16,false,false,false,false,1><<<PG4, 256>>>(
        p_s, 64, 0, nullptr, wc33, 64, 0, nullptr, nullptr, out, 64, 1);
    bn_final_k<<<64, 32>>>(1024, 9);
    norm_out_k<<<SZ64 / 1024, 256>>>(out);
}